// round 3
// baseline (speedup 1.0000x reference)
#include <cuda_runtime.h>

#define BB 32
#define PP 4096
#define QQ 64
#define DD 128
#define NT 9
#define TILE 456
#define NEGBIG (-1e30f)
#define POSBIG (1e30f)

#define SMEM_FLOATS 23568
#define SMEM_BYTES (SMEM_FLOATS * 4)

// scratch (no allocations allowed)
__device__ float g_Vt[BB * DD * QQ];          // Vt[b][d][q] = sum_e W[d,e]*U[b,q,e]
__device__ float g_part[BB * NT * 1024];      // per (b,tile) partials

// ---------------------------------------------------------------------------
// Kernel 1: Vt[b][d][q]. grid (8, 32), 256 threads; block = one batch, 16 d.
// ---------------------------------------------------------------------------
__global__ void vt_kernel(const float* __restrict__ U, const float* __restrict__ W) {
    __shared__ float U_s[QQ * 129];   // padded, conflict-free column reads
    __shared__ float W_s[16 * DD];
    int b = blockIdx.y;
    int dbase = blockIdx.x * 16;
    int tid = threadIdx.x;

    const float* Ub = U + (size_t)b * QQ * DD;
    for (int i = tid; i < QQ * DD; i += 256) {
        int q = i >> 7, e = i & 127;
        U_s[q * 129 + e] = Ub[i];
    }
    for (int i = tid; i < 16 * DD; i += 256)
        W_s[i] = W[(size_t)dbase * DD + i];
    __syncthreads();

    int q = tid & 63;
    int dg = tid >> 6;   // warp-uniform -> W_s broadcast
    float acc[4] = {0.f, 0.f, 0.f, 0.f};
#pragma unroll 4
    for (int e = 0; e < DD; e++) {
        float u = U_s[q * 129 + e];
#pragma unroll
        for (int k = 0; k < 4; k++)
            acc[k] += u * W_s[(dg * 4 + k) * DD + e];
    }
#pragma unroll
    for (int k = 0; k < 4; k++)
        g_Vt[((size_t)b * DD + dbase + dg * 4 + k) * QQ + q] = acc[k];
}

// ---------------------------------------------------------------------------
// Kernel 2: fused attention + pooling partials.
// grid (NT, 32), 256 threads, dynamic smem SMEM_BYTES, 2 CTA/SM.
// Each warp register-blocks 4 consecutive p rows. Lane owns q-pair
// (2*lane, 2*lane+1) in the S phase, d-quad (4*lane..+3) elsewhere.
// ---------------------------------------------------------------------------
__global__ void __launch_bounds__(256, 2) main_kernel(
    const float* __restrict__ H, const float* __restrict__ U,
    const float* __restrict__ Mm, const int* __restrict__ tok)
{
    extern __shared__ float sm[];
    float* Vt_s = sm;                 // 128*64 = 8192 floats
    float* U_s  = sm + 8192;          // 64*128 = 8192
    float* h_s  = sm + 16384;         // 8 warps * 4 rows * 128 = 4096
    float* w_s  = sm + 20480;         // 8 warps * 4 rows * 64  = 2048
    float* red  = sm + 22528;         // 8 * 128 = 1024
    float* mzs  = sm + 23552;         // 16

    int t = blockIdx.x, b = blockIdx.y;
    int pstart = t * TILE;
    int pend   = min(pstart + TILE, PP);
    int tid = threadIdx.x, wid = tid >> 5, lane = tid & 31;

    // stage Vt and U
    const float* Vtb = g_Vt + (size_t)b * DD * QQ;
    for (int i = tid; i < (DD * QQ) / 4; i += 256)
        ((float4*)Vt_s)[i] = ((const float4*)Vtb)[i];
    const float* Ub = U + (size_t)b * QQ * DD;
    for (int i = tid; i < (QQ * DD) / 4; i += 256)
        ((float4*)U_s)[i] = ((const float4*)Ub)[i];
    __syncthreads();

    // per-warp running partials (lane covers d = 4*lane + j)
    float pm_h[4], pm_c[4], pm_hc[4], pm_m[4], mxh[4], mnh[4], qacc[4];
#pragma unroll
    for (int j = 0; j < 4; j++) {
        pm_h[j] = NEGBIG; pm_c[j] = NEGBIG; pm_hc[j] = NEGBIG; pm_m[j] = NEGBIG;
        mxh[j] = NEGBIG;  mnh[j] = POSBIG;  qacc[j] = 0.f;
    }
    float Mw = NEGBIG, Zw = 0.f;

    float* myh = h_s + wid * 4 * DD;
    float* myw = w_s + wid * 4 * QQ;
    int q0 = 2 * lane;

    for (int pg = pstart; pg < pend; pg += 32) {
        int p0 = pg + wid * 4;
        if (p0 >= pend) continue;          // warp-uniform

        // stage 4 H rows (keep lane's d-quad in registers too)
        float4 h4[4];
#pragma unroll
        for (int i = 0; i < 4; i++) {
            int p = min(p0 + i, pend - 1);
            h4[i] = *(const float4*)(H + ((size_t)b * PP + p) * DD + 4 * lane);
            *(float4*)(myh + i * DD + 4 * lane) = h4[i];
        }
        __syncwarp();

        // ---- S phase: s[i][j] = H[p_i] . Vt[:, q0+j] ----
        float s[4][2];
#pragma unroll
        for (int i = 0; i < 4; i++) { s[i][0] = 0.f; s[i][1] = 0.f; }
#pragma unroll 4
        for (int d = 0; d < DD; d += 2) {
            float2 v0 = *(const float2*)(Vt_s + d * QQ + q0);
            float2 v1 = *(const float2*)(Vt_s + (d + 1) * QQ + q0);
#pragma unroll
            for (int i = 0; i < 4; i++) {
                float2 hh = *(const float2*)(myh + i * DD + d);   // broadcast
                s[i][0] += hh.x * v0.x; s[i][1] += hh.x * v0.y;
                s[i][0] += hh.y * v1.x; s[i][1] += hh.y * v1.y;
            }
        }

        // ---- softmax over q (warp reduce), save row max for q2c ----
        float rowm[4];
#pragma unroll
        for (int i = 0; i < 4; i++) {
            float m = fmaxf(s[i][0], s[i][1]);
#pragma unroll
            for (int off = 16; off > 0; off >>= 1)
                m = fmaxf(m, __shfl_xor_sync(0xffffffffu, m, off));
            float e0 = __expf(s[i][0] - m);
            float e1 = __expf(s[i][1] - m);
            float ss = e0 + e1;
#pragma unroll
            for (int off = 16; off > 0; off >>= 1)
                ss += __shfl_xor_sync(0xffffffffu, ss, off);
            float inv = 1.f / ss;
            *(float2*)(myw + i * QQ + q0) = make_float2(e0 * inv, e1 * inv);
            rowm[i] = m;
        }
        __syncwarp();

        // ---- c2q: c[i][j] = sum_q w[i][q] * U[q][4*lane+j] ----
        float c[4][4];
#pragma unroll
        for (int i = 0; i < 4; i++) { c[i][0] = c[i][1] = c[i][2] = c[i][3] = 0.f; }
#pragma unroll 2
        for (int q = 0; q < QQ; q++) {
            float4 u4 = *(const float4*)(U_s + q * DD + 4 * lane);
#pragma unroll
            for (int i = 0; i < 4; i++) {
                float wq = myw[i * QQ + q];                        // broadcast
                c[i][0] += wq * u4.x; c[i][1] += wq * u4.y;
                c[i][2] += wq * u4.z; c[i][3] += wq * u4.w;
            }
        }

        // ---- online q2c stats (no pad mask) + pooled maxes (pad-masked) ----
#pragma unroll
        for (int i = 0; i < 4; i++) {
            int p = p0 + i;
            if (p < pend) {
                float nM = fmaxf(Mw, rowm[i]);
                float a  = __expf(Mw - nM);
                float e  = __expf(rowm[i] - nM);
                float hv[4] = {h4[i].x, h4[i].y, h4[i].z, h4[i].w};
#pragma unroll
                for (int j = 0; j < 4; j++) qacc[j] = qacc[j] * a + e * hv[j];
                Zw = Zw * a + e;
                Mw = nM;

                int tk = tok[(size_t)b * PP + p];     // int32 token ids
                if (tk != 0) {
                    float4 m4 = *(const float4*)(Mm + ((size_t)b * PP + p) * DD + 4 * lane);
                    float mv[4] = {m4.x, m4.y, m4.z, m4.w};
#pragma unroll
                    for (int j = 0; j < 4; j++) {
                        pm_h[j]  = fmaxf(pm_h[j],  hv[j]);
                        pm_c[j]  = fmaxf(pm_c[j],  c[i][j]);
                        pm_hc[j] = fmaxf(pm_hc[j], hv[j] * c[i][j]);
                        pm_m[j]  = fmaxf(pm_m[j],  mv[j]);
                        mxh[j]   = fmaxf(mxh[j],   hv[j]);
                        mnh[j]   = fminf(mnh[j],   hv[j]);
                    }
                }
            }
        }
        __syncwarp();
    }

    // ---------------- block reduction -> tile partials ----------------
    __syncthreads();
    if (lane == 0) { mzs[wid * 2] = Mw; mzs[wid * 2 + 1] = Zw; }
    __syncthreads();
    float Mb = mzs[0];
#pragma unroll
    for (int w = 1; w < 8; w++) Mb = fmaxf(Mb, mzs[2 * w]);

    float* pout = g_part + ((size_t)b * NT + t) * 1024;
    float sc = __expf(Mw - Mb);   // Mw uniform within warp

    // qacc: scaled sum across warps
    *(float4*)(red + wid * DD + 4 * lane) =
        make_float4(qacc[0] * sc, qacc[1] * sc, qacc[2] * sc, qacc[3] * sc);
    __syncthreads();
    if (tid < DD) {
        float r = 0.f;
#pragma unroll
        for (int w = 0; w < 8; w++) r += red[w * DD + tid];
        pout[tid] = r;
    }

#define BLK_MAXRED(arr, off)                                                   \
    do {                                                                       \
        __syncthreads();                                                       \
        *(float4*)(red + wid * DD + 4 * lane) =                                \
            make_float4((arr)[0], (arr)[1], (arr)[2], (arr)[3]);               \
        __syncthreads();                                                       \
        if (tid < DD) {                                                        \
            float r = red[tid];                                                \
            for (int w = 1; w < 8; w++) r = fmaxf(r, red[w * DD + tid]);       \
            pout[(off) + tid] = r;                                             \
        }                                                                      \
    } while (0)

    BLK_MAXRED(pm_h, 128);
    BLK_MAXRED(pm_c, 256);
    BLK_MAXRED(pm_hc, 384);
    BLK_MAXRED(pm_m, 512);
    BLK_MAXRED(mxh, 640);

    // min reduction: mnh(768)
    __syncthreads();
    *(float4*)(red + wid * DD + 4 * lane) = make_float4(mnh[0], mnh[1], mnh[2], mnh[3]);
    __syncthreads();
    if (tid < DD) {
        float r = red[tid];
#pragma unroll
        for (int w = 1; w < 8; w++) r = fminf(r, red[w * DD + tid]);
        pout[768 + tid] = r;
    }

    if (tid == 0) {
        float Zt = 0.f;
#pragma unroll
        for (int w = 0; w < 8; w++) Zt += mzs[2 * w + 1] * __expf(mzs[2 * w] - Mb);
        pout[896] = Mb;
        pout[897] = Zt;
    }
}

// ---------------------------------------------------------------------------
// Kernel 3: per-batch tile combine + classifier. grid 32, 128 threads.
// ---------------------------------------------------------------------------
__global__ void finalize_kernel(const float* __restrict__ Wcls, float* __restrict__ out) {
    int b = blockIdx.x, d = threadIdx.x;
    const float* base = g_part + (size_t)b * NT * 1024;

    float Mg = NEGBIG;
#pragma unroll
    for (int t = 0; t < NT; t++) Mg = fmaxf(Mg, base[t * 1024 + 896]);

    float Z = 0.f, qa = 0.f;
    float ph = NEGBIG, pc = NEGBIG, phc = NEGBIG, pm = NEGBIG, xh = NEGBIG, nh = POSBIG;
#pragma unroll
    for (int t = 0; t < NT; t++) {
        const float* pt = base + t * 1024;
        float scv = __expf(pt[896] - Mg);
        Z  += pt[897] * scv;
        qa += pt[d] * scv;
        ph  = fmaxf(ph,  pt[128 + d]);
        pc  = fmaxf(pc,  pt[256 + d]);
        phc = fmaxf(phc, pt[384 + d]);
        pm  = fmaxf(pm,  pt[512 + d]);
        xh  = fmaxf(xh,  pt[640 + d]);
        nh  = fminf(nh,  pt[768 + d]);
    }
    float q2c = qa / Z;
    float phq = fmaxf(q2c * xh, q2c * nh);   // masked max_p of H[p,d]*q2c[d]

    float o0 = ph  * Wcls[2 * d]
             + pc  * Wcls[2 * (128 + d)]
             + phc * Wcls[2 * (256 + d)]
             + phq * Wcls[2 * (384 + d)]
             + pm  * Wcls[2 * (512 + d)];
    float o1 = ph  * Wcls[2 * d + 1]
             + pc  * Wcls[2 * (128 + d) + 1]
             + phc * Wcls[2 * (256 + d) + 1]
             + phq * Wcls[2 * (384 + d) + 1]
             + pm  * Wcls[2 * (512 + d) + 1];

    __shared__ float r0[128], r1[128];
    r0[d] = o0; r1[d] = o1;
    __syncthreads();
    for (int s = 64; s > 0; s >>= 1) {
        if (d < s) { r0[d] += r0[d + s]; r1[d] += r1[d + s]; }
        __syncthreads();
    }
    if (d == 0) { out[b * 2] = r0[0]; out[b * 2 + 1] = r1[0]; }
}

// ---------------------------------------------------------------------------
extern "C" void kernel_launch(void* const* d_in, const int* in_sizes, int n_in,
                              void* d_out, int out_size) {
    const float* H     = (const float*)d_in[0];
    const float* U     = (const float*)d_in[1];
    const float* Mm    = (const float*)d_in[2];
    const int*   tok   = (const int*)d_in[3];     // int64 in the ref, int32 on the wire (JAX x64 off)
    const float* Wattn = (const float*)d_in[4];
    const float* Wcls  = (const float*)d_in[5];
    float*       out   = (float*)d_out;

    cudaFuncSetAttribute(main_kernel, cudaFuncAttributeMaxDynamicSharedMemorySize, SMEM_BYTES);

    vt_kernel<<<dim3(8, BB), 256>>>(U, Wattn);
    main_kernel<<<dim3(NT, BB), 256, SMEM_BYTES>>>(H, U, Mm, tok);
    finalize_kernel<<<BB, 128>>>(Wcls, out);
}